// round 12
// baseline (speedup 1.0000x reference)
#include <cuda_runtime.h>
#include <math.h>

#define BB 16
#define DD 768
#define LL 96
#define CHUNK 128
#define NCHUNK 6
#define XPITCH 132   // 128 + 4 pad (bank-conflict-free staging)
#define SOFT_ELEMS (BB*LL*LL*DD)        // 113246208
#define HW_ELEMS   (BB*LL*LL*3)         // 442368
#define NINVALID (LL*(LL-1)/2)          // 4560
#define SPAN_SMEM_FLOATS (LL*XPITCH + LL + 192)

__constant__ float c_posw[6] = {2.0f, 1.5f, 1.0f, 0.8f, 0.3f, 0.5f};
__constant__ float c_depw[6] = {2.0f, 1.5f, 1.5f, 1.2f, 1.0f, 0.5f};

__device__ float g_E[BB*LL];     // exp(base/TEMP) per token
__device__ float g_S[BB*DD];     // per-(b,d) column sum of embeds

__device__ __forceinline__ int chain_len(int c2) {
    int m = min(c2, 190 - c2);
    return (m >> 1) + 1;
}

// ---------------------------------------------------------------------------
// prep: grid (97, 16), block 256.
//  x < 96 : warp-per-d column sums (x==0 also computes degree/E -> g_E)
//  x == 96: aux block — thread t walks chain c2=t incrementally, emits hw/hi;
//           then strided fill of invalid hw=0 / hi=-1 rows.
// ---------------------------------------------------------------------------
__global__ void prep_kernel(const float* __restrict__ x, const int* __restrict__ par,
                            const int* __restrict__ pos, const int* __restrict__ dep,
                            float* __restrict__ out, int write_aux) {
    int b = blockIdx.y;
    int tid = threadIdx.x;

    __shared__ int   cnt[LL];
    __shared__ float sE[LL], sB[LL], sM2[192], sMm[192];

    if (blockIdx.x < 96) {
        int w = tid >> 5, lane = tid & 31;
        int d = blockIdx.x * 8 + w;
        const float* p = x + ((size_t)b*DD + d)*LL;
        float s = p[lane] + p[lane + 32] + p[lane + 64];
#pragma unroll
        for (int off = 16; off; off >>= 1) s += __shfl_down_sync(0xffffffffu, s, off);
        if (lane == 0) g_S[b*DD + d] = s;

        if (blockIdx.x == 0) {
            if (tid < LL) cnt[tid] = 0;
            __syncthreads();
            if (tid < LL) atomicAdd(&cnt[par[b*LL + tid]], 1);
            __syncthreads();
            if (tid < LL) {
                float t0 = __fmul_rn(1.5f, (float)cnt[tid]);
                float t1 = __fadd_rn(2.0f, t0);
                float t2 = __fadd_rn(t1, __fmul_rn(0.8f, c_posw[pos[b*LL + tid]]));
                float base = __fadd_rn(t2, __fmul_rn(0.5f, c_depw[dep[b*LL + tid]]));
                g_E[b*LL + tid] = expf(base / 0.7f);
            }
        }
        return;
    }

    // ---------------- aux block ----------------
    if (!write_aux) return;

    if (tid < LL) cnt[tid] = 0;
    __syncthreads();
    if (tid < LL) atomicAdd(&cnt[par[b*LL + tid]], 1);
    for (int k = tid; k < 191; k += 256) {
        float denom = __fadd_rn(1.0f, 0.5f*(float)k);   // exact
        float med = __fdiv_rn(0.5f, denom);             // JAX medoid bits
        sMm[k] = med;
        sM2[k] = expf(med / 0.7f);
    }
    __syncthreads();
    if (tid < LL) {
        // XLA elementwise, no fma contraction
        float t0 = __fmul_rn(1.5f, (float)cnt[tid]);
        float t1 = __fadd_rn(2.0f, t0);
        float t2 = __fadd_rn(t1, __fmul_rn(0.8f, c_posw[pos[b*LL + tid]]));
        float base = __fadd_rn(t2, __fmul_rn(0.5f, c_depw[dep[b*LL + tid]]));
        sB[tid] = base;
        sE[tid] = expf(base / 0.7f);
    }
    __syncthreads();

    float* hw_base = out + SOFT_ELEMS;
    float* hi_base = out + SOFT_ELEMS + HW_ELEMS;

    if (tid <= 190) {
        int c2 = tid;
        int l = c2 >> 1;
        int r = c2 - l;
        int kl = c2 - 2*l;
        int kr = 2*r - c2;

        float za = 0.f;
        float y0 = -1e30f, y1 = -1e30f, y2 = -1e30f;
        int   i0 = 0x7fffffff, i1 = 0x7fffffff, i2 = 0x7fffffff;

        auto addtok = [&](int t, int k) {
            za += sE[t] * sM2[k] - 1.0f;
            float y = __fadd_rn(sB[t], sMm[k]);   // JAX score bits (order key)
            bool q0 = (y > y0) || (y == y0 && t < i0);
            bool q1 = (y > y1) || (y == y1 && t < i1);
            bool q2 = (y > y2) || (y == y2 && t < i2);
            if (q0)      { y2=y1; i2=i1; y1=y0; i1=i0; y0=y; i0=t; }
            else if (q1) { y2=y1; i2=i1; y1=y; i1=t; }
            else if (q2) { y2=y;  i2=t; }
        };

        addtok(l, kl);
        if (r != l) addtok(r, kr);

        float* hw = hw_base + (size_t)((b*LL + l)*LL + r)*3;
        float* hi = hw_base + HW_ELEMS + (size_t)((b*LL + l)*LL + r)*3;
        const ptrdiff_t HDELTA = -(ptrdiff_t)(LL-1)*3;

        while (1) {
            float invZ = __fdividef(1.0f, (float)LL + za);
            int len = r - l + 1;
            int k0 = 2*i0 - c2; k0 = k0 < 0 ? -k0 : k0;
            float w0 = sE[i0] * sM2[k0];
            float hv1, hv2, fi1, fi2;
            if (len >= 3) {
                int k1 = 2*i1 - c2; k1 = k1 < 0 ? -k1 : k1;
                int k2v = 2*i2 - c2; k2v = k2v < 0 ? -k2v : k2v;
                hv1 = sE[i1]*sM2[k1]*invZ;  fi1 = (float)i1;
                hv2 = sE[i2]*sM2[k2v]*invZ; fi2 = (float)i2;
            } else if (len == 2) {
                int k1 = 2*i1 - c2; k1 = k1 < 0 ? -k1 : k1;
                hv1 = sE[i1]*sM2[k1]*invZ;  fi1 = (float)i1;
                hv2 = invZ;                 fi2 = (l > 0) ? 0.f : (float)(r+1);
            } else {
                hv1 = invZ; hv2 = invZ;
                if (l == 0)      { fi1 = 1.f; fi2 = 2.f; }
                else if (l == 1) { fi1 = 0.f; fi2 = 2.f; }
                else             { fi1 = 0.f; fi2 = 1.f; }
            }
            hw[0] = w0*invZ; hw[1] = hv1; hw[2] = hv2;
            hi[0] = (float)i0; hi[1] = fi1; hi[2] = fi2;

            if (l == 0 || r == LL-1) break;
            --l; ++r; kl += 2; kr += 2;
            addtok(l, kl);
            addtok(r, kr);
            hw += HDELTA; hi += HDELTA;
        }
    }

    // invalid aux rows: hw = 0, hi = -1
    for (int j = tid; j < NINVALID; j += 256) {
        int l = (int)((1.0f + sqrtf(8.0f*(float)j + 1.0f)) * 0.5f);
        while (l*(l-1)/2 > j) --l;
        while (l*(l+1)/2 <= j) ++l;
        int r = j - l*(l-1)/2;
        size_t row = (size_t)(b*LL + l)*LL + r;
        float* hw = hw_base + row*3;
        float* hi = hi_base + row*3;
        hw[0] = 0.f; hw[1] = 0.f; hw[2] = 0.f;
        hi[0] = -1.f; hi[1] = -1.f; hi[2] = -1.f;
    }
}

// ---------------------------------------------------------------------------
// lean per-warp center-chain walker (soft_heads only)
// ---------------------------------------------------------------------------
__device__ __forceinline__ void run_chain(
    const float* __restrict__ x_sm, const float* __restrict__ E_sm,
    const float* __restrict__ M2, const float4 Sa,
    float* __restrict__ out, int b, int c2, int chunk, int lane)
{
    const int dlo = (lane << 2);
    int l = c2 >> 1;
    int r = c2 - l;
    int kl = c2 - 2*l;   // 0 or 1
    int kr = 2*r - c2;   // 0 or 1

    const float* xl = x_sm + l*XPITCH + dlo;
    const float* xr = x_sm + r*XPITCH + dlo;

    float4 A = make_float4(0.f,0.f,0.f,0.f);
    float za = 0.f;

    auto addtok = [&](int t, int k, const float* xrow) {
        float a = E_sm[t] * M2[k] - 1.0f;
        za += a;
        float4 xa = *(const float4*)xrow;
        A.x += a*xa.x; A.y += a*xa.y; A.z += a*xa.z; A.w += a*xa.w;
    };

    addtok(l, kl, xl);
    if (r != l) addtok(r, kr, xr);

    float* o = out + ((size_t)((b*LL + l)*LL + r))*DD + chunk*CHUNK + dlo;
    const ptrdiff_t ODELTA = -(ptrdiff_t)(LL-1)*DD;

    while (1) {
        float invZ = __fdividef(1.0f, (float)LL + za);
        float4 o0;
        o0.x = (A.x + Sa.x)*invZ; o0.y = (A.y + Sa.y)*invZ;
        o0.z = (A.z + Sa.z)*invZ; o0.w = (A.w + Sa.w)*invZ;
        __stcs((float4*)o, o0);

        if (l == 0 || r == LL-1) break;
        --l; ++r; kl += 2; kr += 2;
        xl -= XPITCH; xr += XPITCH;
        addtok(l, kl, xl);
        addtok(r, kr, xr);
        o += ODELTA;
    }
}

// ---------------------------------------------------------------------------
// span kernel: grid (6, 6, 16) = 576 CTAs, block 384, 4 CTA/SM -> ONE WAVE.
// Warp v = g*12+wid in [0,72): chains {v, v+72, v+144<=190} (60-73 spans),
// then (128 - load_v) invalid zero rows -> every warp stores exactly 64 KB.
// ---------------------------------------------------------------------------
__global__ void __launch_bounds__(384, 4)
span_kernel(const float* __restrict__ x, float* __restrict__ out) {
    int g = blockIdx.x, chunk = blockIdx.y, b = blockIdx.z;
    int tid = threadIdx.x;

    extern __shared__ float sm[];
    float* x_sm = sm;                 // [96][132]
    float* E_sm = sm + LL*XPITCH;     // [96]
    float* M2   = E_sm + LL;          // [192]

    const float* gx = x + ((size_t)b*DD + (size_t)chunk*CHUNK)*LL;
    for (int i = tid; i < CHUNK*LL; i += 384) {
        int d = i / LL;
        int t = i - d*LL;
        x_sm[t*XPITCH + d] = gx[i];
    }
    for (int k = tid; k < 191; k += 384) {
        float denom = __fadd_rn(1.0f, 0.5f*(float)k);
        M2[k] = expf(__fdiv_rn(0.5f, denom) / 0.7f);
    }
    if (tid < LL) E_sm[tid] = g_E[b*LL + tid];
    __syncthreads();

    int wid = tid >> 5, lane = tid & 31;
    int v = g*12 + wid;                     // [0,72)

    const int dlo = (lane << 2);
    const float* Sp = g_S + b*DD + chunk*CHUNK + dlo;
    float4 Sa = *(const float4*)Sp;

    run_chain(x_sm, E_sm, M2, Sa, out, b, v,      chunk, lane);
    run_chain(x_sm, E_sm, M2, Sa, out, b, v + 72, chunk, lane);
    if (v + 144 <= 190)
        run_chain(x_sm, E_sm, M2, Sa, out, b, v + 144, chunk, lane);

    // ---- zero duty: contiguous block of invalid rows, anti-balanced ----
    int load_v = chain_len(v) + chain_len(v + 72)
               + ((v + 144 <= 190) ? chain_len(v + 144) : 0);
    int start = 0;
    for (int v2 = 0; v2 < v; ++v2) {
        int lv = chain_len(v2) + chain_len(v2 + 72)
               + ((v2 + 144 <= 190) ? chain_len(v2 + 144) : 0);
        start += 128 - lv;
    }
    int rows = 128 - load_v;

    int j = start;
    int l = (int)((1.0f + sqrtf(8.0f*(float)j + 1.0f)) * 0.5f);
    while (l*(l-1)/2 > j) --l;
    while (l*(l+1)/2 <= j) ++l;
    int r = j - l*(l-1)/2;

    float4 zz = make_float4(0.f, 0.f, 0.f, 0.f);
    float* zp = out + ((size_t)(b*LL + l)*LL + r)*DD + chunk*CHUNK + dlo;
    for (int n = 0; n < rows; ++n) {
        __stcs((float4*)zp, zz);
        ++r; zp += DD;
        if (r == l) {
            ++l; r = 0;
            zp = out + ((size_t)(b*LL + l)*LL)*DD + chunk*CHUNK + dlo;
        }
    }
}

// ---------------------------------------------------------------------------
extern "C" void kernel_launch(void* const* d_in, const int* in_sizes, int n_in,
                              void* d_out, int out_size) {
    const float* x  = (const float*)d_in[0];
    const int* par  = (const int*)d_in[1];
    const int* pos  = (const int*)d_in[2];
    const int* dep  = (const int*)d_in[3];
    float* out = (float*)d_out;

    int write_aux = (out_size >= SOFT_ELEMS + 2*HW_ELEMS) ? 1 : 0;

    prep_kernel<<<dim3(97, BB), 256>>>(x, par, pos, dep, out, write_aux);

    int smem = SPAN_SMEM_FLOATS * 4;
    cudaFuncSetAttribute(span_kernel, cudaFuncAttributeMaxDynamicSharedMemorySize, smem);
    span_kernel<<<dim3(6, NCHUNK, BB), 384, smem>>>(x, out);
}